// round 1
// baseline (speedup 1.0000x reference)
#include <cuda_runtime.h>
#include <cuda_bf16.h>
#include <math.h>

#define T_  12
#define M_  2048
#define B_  2
#define N_  1024
#define DIN 64
#define DH  128
#define DT  16
#define DO  32
#define NJC 8          // j-chunks per column (2048/256)
#define CAPC 32        // edge capacity per (column, j-chunk)

// ---------------- device scratch (sanctioned __device__ globals) ---------------
__device__ int   g_mdtype;                    // 0=uint8, 1=int32, 2=float
__device__ int   g_mask[T_ * M_];             // 0/1 per (t, node)
__device__ int   g_list[T_ * M_];             // compacted masked node ids per t
__device__ int   g_mcnt[T_];                  // masked count per t
__device__ int   g_cnt8[T_ * M_ * NJC];       // nnz per (t, col i, j-chunk)
__device__ int   g_col [T_ * M_ * NJC * CAPC];// source node j lists
__device__ float g_nrm [T_ * M_];
__device__ float g_z   [T_ * M_ * DH];        // z = nrm * (h @ W)   (by node id)
__device__ float g_h   [T_ * M_ * DH];        // GCN layer output    (by node id)
__device__ float g_Q   [T_ * M_ * DH];        // compacted by list position
__device__ float g_K   [T_ * M_ * DH];
__device__ float g_V   [T_ * M_ * DH];
__device__ float g_agg [T_ * M_ * DH];        // compacted by list position
__device__ float g_qt  [T_ * DH];             // per-t time-derived Q bias
__device__ float g_kt  [T_ * DH];
__device__ float g_vt  [T_ * DH];

// ---------------- mask dtype detection ----------------
__global__ void k_detect(const void* p) {
    const int*   wi = (const int*)p;
    const float* wf = (const float*)p;
    int oki = 1, okf = 1;
    for (int r = 0; r < 8; r++) {
        int idx = r * 256 + threadIdx.x;   // 2048 words, within 24576-byte buffer
        int w  = wi[idx];
        float f = wf[idx];
        oki &= (w == 0 || w == 1);
        okf &= (f == 0.0f || f == 1.0f);
    }
    oki = __syncthreads_and(oki);
    okf = __syncthreads_and(okf);
    if (threadIdx.x == 0) g_mdtype = okf ? 2 : (oki ? 1 : 0);
}

// ---------------- materialize mask [T,M] from ego_mask [B,T,N] ----------------
__global__ void k_mask(const void* em) {
    int idx = blockIdx.x * 256 + threadIdx.x;    // over T_*M_
    int t = idx >> 11, m = idx & (M_ - 1);
    int b = m >> 10, n = m & (N_ - 1);
    int src = (b * T_ + t) * N_ + n;
    int dt = g_mdtype;
    int v;
    if (dt == 1)      v = ((const int*)em)[src] != 0;
    else if (dt == 2) v = ((const float*)em)[src] != 0.0f;
    else              v = ((const unsigned char*)em)[src] != 0;
    g_mask[idx] = v;
}

// ---------------- deterministic stream compaction (per t) ----------------
__global__ void __launch_bounds__(1024) k_compact() {
    int t = blockIdx.x, tid = threadIdx.x;
    __shared__ int wsum[32];
    __shared__ int sbase;
    if (tid == 0) sbase = 0;
    __syncthreads();
    for (int half = 0; half < 2; half++) {
        int i = half * 1024 + tid;
        int mv = g_mask[t * M_ + i];
        unsigned b = __ballot_sync(0xffffffffu, mv);
        int lane = tid & 31, wid = tid >> 5;
        if (lane == 0) wsum[wid] = __popc(b);
        __syncthreads();
        int woff = 0;
        for (int w = 0; w < wid; w++) woff += wsum[w];
        if (mv) g_list[t * M_ + sbase + woff + __popc(b & ((1u << lane) - 1u))] = i;
        __syncthreads();
        if (tid == 0) {
            int tot = 0;
            for (int w = 0; w < 32; w++) tot += wsum[w];
            sbase += tot;
        }
        __syncthreads();
    }
    if (tid == 0) g_mcnt[t] = sbase;
}

// ---------------- edge extraction: A scan, per-(column, j-chunk) lists ----------------
__global__ void k_edges(const float* __restrict__ A) {
    int t = blockIdx.x, jc = blockIdx.y, ic = blockIdx.z;
    int i = ic * 256 + threadIdx.x;
    __shared__ int mj[256];
    int jbase = jc * 256;
    mj[threadIdx.x] = g_mask[t * M_ + jbase + threadIdx.x];
    __syncthreads();
    int mi = g_mask[t * M_ + i];
    int cnt = 0;
    int* cols = g_col + ((size_t)((t * M_ + i) * NJC + jc)) * CAPC;
    if (mi) {
        const float* Ab = A + (size_t)(t * M_ + jbase) * M_ + i;
        for (int jj = 0; jj < 256; jj++) {
            float a = Ab[(size_t)jj * M_];
            if (a != 0.0f && mj[jj] && cnt < CAPC) cols[cnt++] = jbase + jj;
        }
    }
    g_cnt8[(t * M_ + i) * NJC + jc] = cnt;
}

// ---------------- degree norm ----------------
__global__ void k_nrm() {
    int idx = blockIdx.x * 256 + threadIdx.x;   // over T_*M_
    float nv = 0.0f;
    if (g_mask[idx]) {
        int c = 1; // self-loop
        #pragma unroll
        for (int jc = 0; jc < NJC; jc++) c += g_cnt8[idx * NJC + jc];
        nv = rsqrtf((float)c);
    }
    g_nrm[idx] = nv;
}

// ---------------- per-t time-feature biases for Q/K/V ----------------
__global__ void k_tbias(const float* __restrict__ tw, const float* __restrict__ tb,
                        const float* __restrict__ qw, const float* __restrict__ qb,
                        const float* __restrict__ kw, const float* __restrict__ kb,
                        const float* __restrict__ vw, const float* __restrict__ vb) {
    int t = blockIdx.x, f = threadIdx.x;
    float tv[DT];
    #pragma unroll
    for (int d = 0; d < DT; d++) tv[d] = sinf((float)t * tw[d] + tb[d]);
    float aq = qb[f], ak = kb[f], av = vb[f];
    #pragma unroll
    for (int d = 0; d < DT; d++) {
        aq += tv[d] * qw[(DH + d) * DH + f];
        ak += tv[d] * kw[(DH + d) * DH + f];
        av += tv[d] * vw[(DH + d) * DH + f];
    }
    g_qt[t * DH + f] = aq;
    g_kt[t * DH + f] = ak;
    g_vt[t * DH + f] = av;
}

// ---------------- z1 = nrm * (x @ W1), masked nodes only ----------------
__global__ void k_z1(const float* __restrict__ x, const float* __restrict__ w1) {
    int t = blockIdx.x, lp = blockIdx.y;
    if (lp >= g_mcnt[t]) return;
    int i = g_list[t * M_ + lp];
    __shared__ float xs[DIN];
    int f = threadIdx.x;
    if (f < DIN) xs[f] = x[(size_t)(t * M_ + i) * DIN + f];
    __syncthreads();
    float acc = 0.0f;
    #pragma unroll 8
    for (int d = 0; d < DIN; d++) acc += xs[d] * w1[d * DH + f];
    g_z[(size_t)(t * M_ + i) * DH + f] = g_nrm[t * M_ + i] * acc;
}

// ---------------- z2 = nrm * (h @ W2) ----------------
__global__ void k_z2(const float* __restrict__ w2) {
    int t = blockIdx.x, lp = blockIdx.y;
    if (lp >= g_mcnt[t]) return;
    int i = g_list[t * M_ + lp];
    __shared__ float hs[DH];
    int f = threadIdx.x;
    hs[f] = g_h[(size_t)(t * M_ + i) * DH + f];
    __syncthreads();
    float acc = 0.0f;
    #pragma unroll 8
    for (int d = 0; d < DH; d++) acc += hs[d] * w2[d * DH + f];
    g_z[(size_t)(t * M_ + i) * DH + f] = g_nrm[t * M_ + i] * acc;
}

// ---------------- sparse aggregation + bias + ReLU: h = relu(nrm*(sum z) + b) ----------------
__global__ void k_spmm(const float* __restrict__ bias) {
    int t = blockIdx.x, lp = blockIdx.y;
    if (lp >= g_mcnt[t]) return;
    int i = g_list[t * M_ + lp];
    int f = threadIdx.x;
    float acc = g_z[(size_t)(t * M_ + i) * DH + f];  // self-loop term
    const int* c8 = g_cnt8 + (t * M_ + i) * NJC;
    #pragma unroll
    for (int jc = 0; jc < NJC; jc++) {
        int c = c8[jc];
        const int* cl = g_col + ((size_t)((t * M_ + i) * NJC + jc)) * CAPC;
        for (int e = 0; e < c; e++) {
            int j = cl[e];
            acc += g_z[(size_t)(t * M_ + j) * DH + f];
        }
    }
    g_h[(size_t)(t * M_ + i) * DH + f] =
        fmaxf(g_nrm[t * M_ + i] * acc + bias[f], 0.0f);
}

// ---------------- Q/K/V for masked nodes, stored compacted ----------------
__global__ void k_qkv(const float* __restrict__ qw, const float* __restrict__ kw,
                      const float* __restrict__ vw) {
    int t = blockIdx.x, lp = blockIdx.y;
    if (lp >= g_mcnt[t]) return;
    int i = g_list[t * M_ + lp];
    __shared__ float hs[DH];
    int f = threadIdx.x;
    hs[f] = g_h[(size_t)(t * M_ + i) * DH + f];
    __syncthreads();
    float aq = g_qt[t * DH + f], ak = g_kt[t * DH + f], av = g_vt[t * DH + f];
    #pragma unroll 4
    for (int d = 0; d < DH; d++) {
        float hd = hs[d];
        aq += hd * qw[d * DH + f];
        ak += hd * kw[d * DH + f];
        av += hd * vw[d * DH + f];
    }
    size_t o = (size_t)(t * M_ + lp) * DH + f;
    g_Q[o] = aq; g_K[o] = ak; g_V[o] = av;
}

// ---------------- flash-style attention over masked nodes ----------------
#define QT 32
#define KC 64
extern __shared__ float smattn[];
__global__ void __launch_bounds__(256) k_attn() {
    int t = blockIdx.x;
    int mc = g_mcnt[t];
    int qb = blockIdx.y * QT;
    if (qb >= mc) return;
    float* Qs   = smattn;                 // QT*128
    float* Ks   = Qs + QT * DH;           // KC*128 (reused for V)
    float* S    = Ks + KC * DH;           // QT*KC
    float* rowm = S + QT * KC;            // QT
    float* rowl = rowm + QT;              // QT
    float* rowsc= rowl + QT;              // QT
    int tid = threadIdx.x;
    int nv = min(QT, mc - qb);

    for (int idx = tid; idx < QT * DH; idx += 256) {
        int q = idx >> 7;
        Qs[idx] = (q < nv) ? g_Q[(size_t)(t * M_ + qb + q) * DH + (idx & 127)] : 0.0f;
    }
    if (tid < QT) { rowm[tid] = -1e30f; rowl[tid] = 0.0f; }

    float acc[16];
    #pragma unroll
    for (int j = 0; j < 16; j++) acc[j] = 0.0f;
    int q0 = (tid >> 4) * 2;          // AV + score q pair: 0..30
    int f0 = (tid & 15) * 8;          // AV feature group
    int sk0 = (tid & 15) * 4;         // score k quad: 0..60
    const float scl = 0.08838834764831845f; // 1/sqrt(128)

    for (int kb = 0; kb < mc; kb += KC) {
        int kn = min(KC, mc - kb);
        __syncthreads();
        for (int idx = tid; idx < KC * DH; idx += 256) {
            int k = idx >> 7;
            Ks[idx] = (k < kn) ? g_K[(size_t)(t * M_ + kb + k) * DH + (idx & 127)] : 0.0f;
        }
        __syncthreads();
        // scores: 2q x 4k register tile per thread
        {
            const float4* Qa = (const float4*)(Qs + q0 * DH);
            const float4* Qb = (const float4*)(Qs + (q0 + 1) * DH);
            const float4* K0 = (const float4*)(Ks + (sk0 + 0) * DH);
            const float4* K1 = (const float4*)(Ks + (sk0 + 1) * DH);
            const float4* K2 = (const float4*)(Ks + (sk0 + 2) * DH);
            const float4* K3 = (const float4*)(Ks + (sk0 + 3) * DH);
            float s00=0,s01=0,s02=0,s03=0,s10=0,s11=0,s12=0,s13=0;
            #pragma unroll 4
            for (int d = 0; d < DH / 4; d++) {
                float4 qa = Qa[d], qc = Qb[d];
                float4 k0 = K0[d], k1 = K1[d], k2 = K2[d], k3 = K3[d];
                s00 += qa.x*k0.x + qa.y*k0.y + qa.z*k0.z + qa.w*k0.w;
                s01 += qa.x*k1.x + qa.y*k1.y + qa.z*k1.z + qa.w*k1.w;
                s02 += qa.x*k2.x + qa.y*k2.y + qa.z*k2.z + qa.w*k2.w;
                s03 += qa.x*k3.x + qa.y*k3.y + qa.z*k3.z + qa.w*k3.w;
                s10 += qc.x*k0.x + qc.y*k0.y + qc.z*k0.z + qc.w*k0.w;
                s11 += qc.x*k1.x + qc.y*k1.y + qc.z*k1.z + qc.w*k1.w;
                s12 += qc.x*k2.x + qc.y*k2.y + qc.z*k2.z + qc.w*k2.w;
                s13 += qc.x*k3.x + qc.y*k3.y + qc.z*k3.z + qc.w*k3.w;
            }
            S[q0*KC + sk0+0] = (sk0+0 < kn) ? s00*scl : -1e30f;
            S[q0*KC + sk0+1] = (sk0+1 < kn) ? s01*scl : -1e30f;
            S[q0*KC + sk0+2] = (sk0+2 < kn) ? s02*scl : -1e30f;
            S[q0*KC + sk0+3] = (sk0+3 < kn) ? s03*scl : -1e30f;
            S[(q0+1)*KC + sk0+0] = (sk0+0 < kn) ? s10*scl : -1e30f;
            S[(q0+1)*KC + sk0+1] = (sk0+1 < kn) ? s11*scl : -1e30f;
            S[(q0+1)*KC + sk0+2] = (sk0+2 < kn) ? s12*scl : -1e30f;
            S[(q0+1)*KC + sk0+3] = (sk0+3 < kn) ? s13*scl : -1e30f;
        }
        __syncthreads();
        // online softmax: warp w -> rows 4w..4w+3, 8 lanes per row
        {
            int w = tid >> 5, lane = tid & 31;
            int row = w * 4 + (lane >> 3);
            int l8 = lane & 7;
            float mloc = -1e30f;
            #pragma unroll
            for (int k = l8; k < KC; k += 8) mloc = fmaxf(mloc, S[row*KC + k]);
            #pragma unroll
            for (int o = 4; o >= 1; o >>= 1)
                mloc = fmaxf(mloc, __shfl_xor_sync(0xffffffffu, mloc, o));
            float oldm = rowm[row];
            float newm = fmaxf(oldm, mloc);
            float ssum = 0.0f;
            #pragma unroll
            for (int k = l8; k < KC; k += 8) {
                float p = expf(S[row*KC + k] - newm);
                S[row*KC + k] = p;
                ssum += p;
            }
            #pragma unroll
            for (int o = 4; o >= 1; o >>= 1)
                ssum += __shfl_xor_sync(0xffffffffu, ssum, o);
            if (l8 == 0) {
                float sc = expf(oldm - newm);
                rowsc[row] = sc;
                rowl[row] = rowl[row] * sc + ssum;
                rowm[row] = newm;
            }
        }
        __syncthreads();
        // rescale acc, load V chunk (reusing Ks buffer)
        {
            float sc0 = rowsc[q0], sc1 = rowsc[q0 + 1];
            #pragma unroll
            for (int j = 0; j < 8; j++)  acc[j]     *= sc0;
            #pragma unroll
            for (int j = 0; j < 8; j++)  acc[8 + j] *= sc1;
        }
        for (int idx = tid; idx < KC * DH; idx += 256) {
            int k = idx >> 7;
            Ks[idx] = (k < kn) ? g_V[(size_t)(t * M_ + kb + k) * DH + (idx & 127)] : 0.0f;
        }
        __syncthreads();
        // P @ V : 2q x 8f per thread
        {
            const float* Sq0 = S + q0 * KC;
            const float* Sq1 = S + (q0 + 1) * KC;
            for (int k = 0; k < kn; k++) {
                float p0 = Sq0[k], p1 = Sq1[k];
                const float4* V4 = (const float4*)(Ks + k * DH + f0);
                float4 va = V4[0], vb = V4[1];
                acc[0] += p0*va.x; acc[1] += p0*va.y; acc[2] += p0*va.z; acc[3] += p0*va.w;
                acc[4] += p0*vb.x; acc[5] += p0*vb.y; acc[6] += p0*vb.z; acc[7] += p0*vb.w;
                acc[8] += p1*va.x; acc[9] += p1*va.y; acc[10]+= p1*va.z; acc[11]+= p1*va.w;
                acc[12]+= p1*vb.x; acc[13]+= p1*vb.y; acc[14]+= p1*vb.z; acc[15]+= p1*vb.w;
            }
        }
    }
    __syncthreads();
    if (q0 < nv) {
        float inv = 1.0f / rowl[q0];
        #pragma unroll
        for (int j = 0; j < 8; j++)
            g_agg[(size_t)(t * M_ + qb + q0) * DH + f0 + j] = acc[j] * inv;
    }
    if (q0 + 1 < nv) {
        float inv = 1.0f / rowl[q0 + 1];
        #pragma unroll
        for (int j = 0; j < 8; j++)
            g_agg[(size_t)(t * M_ + qb + q0 + 1) * DH + f0 + j] = acc[8 + j] * inv;
    }
}

// ---------------- epilogue: (agg @ o_w + o_b) @ fc_w + fc_b, scatter to output ----------------
__global__ void k_out(const float* __restrict__ ow, const float* __restrict__ ob,
                      const float* __restrict__ fcw, const float* __restrict__ fcb,
                      float* __restrict__ out) {
    int t = blockIdx.x, lp = blockIdx.y;
    if (lp >= g_mcnt[t]) return;
    int i = g_list[t * M_ + lp];
    __shared__ float as[DH];
    __shared__ float os[DH];
    int f = threadIdx.x;
    as[f] = g_agg[(size_t)(t * M_ + lp) * DH + f];
    __syncthreads();
    float o = ob[f];
    #pragma unroll 8
    for (int d = 0; d < DH; d++) o += as[d] * ow[d * DH + f];
    os[f] = o;
    __syncthreads();
    if (f < DO) {
        float r = fcb[f];
        #pragma unroll 8
        for (int d = 0; d < DH; d++) r += os[d] * fcw[d * DO + f];
        // out[b][n][t][f] with i == b*N+n  ->  (i*T + t)*DO + f
        out[((size_t)i * T_ + t) * DO + f] = r;
    }
}

// ---------------- launch ----------------
extern "C" void kernel_launch(void* const* d_in, const int* in_sizes, int n_in,
                              void* d_out, int out_size) {
    const float* x   = (const float*)d_in[0];
    const float* A   = (const float*)d_in[1];
    const void*  em  = d_in[2];
    const float* w1  = (const float*)d_in[3];
    const float* b1  = (const float*)d_in[4];
    const float* w2  = (const float*)d_in[5];
    const float* b2  = (const float*)d_in[6];
    const float* tw  = (const float*)d_in[7];
    const float* tb  = (const float*)d_in[8];
    const float* qw  = (const float*)d_in[9];
    const float* qb  = (const float*)d_in[10];
    const float* kw  = (const float*)d_in[11];
    const float* kb  = (const float*)d_in[12];
    const float* vw  = (const float*)d_in[13];
    const float* vb  = (const float*)d_in[14];
    const float* ow  = (const float*)d_in[15];
    const float* ob  = (const float*)d_in[16];
    const float* fcw = (const float*)d_in[17];
    const float* fcb = (const float*)d_in[18];

    static bool attr_set = false;
    const int ATTN_SMEM = (QT * DH + KC * DH + QT * KC + 3 * QT) * 4; // 57728 B
    if (!attr_set) {
        cudaFuncSetAttribute(k_attn, cudaFuncAttributeMaxDynamicSharedMemorySize, ATTN_SMEM);
        attr_set = true;
    }

    k_detect<<<1, 256>>>(em);
    k_mask<<<(T_ * M_) / 256, 256>>>(em);
    k_compact<<<T_, 1024>>>();
    k_edges<<<dim3(T_, NJC, M_ / 256), 256>>>(A);
    k_nrm<<<(T_ * M_) / 256, 256>>>();
    k_tbias<<<T_, DH>>>(tw, tb, qw, qb, kw, kb, vw, vb);
    k_z1<<<dim3(T_, M_), DH>>>(x, w1);
    k_spmm<<<dim3(T_, M_), DH>>>(b1);
    k_z2<<<dim3(T_, M_), DH>>>(w2);
    k_spmm<<<dim3(T_, M_), DH>>>(b2);
    k_qkv<<<dim3(T_, M_), DH>>>(qw, kw, vw);
    k_attn<<<dim3(T_, M_ / QT), 256, ATTN_SMEM>>>();
    cudaMemsetAsync(d_out, 0, (size_t)out_size * sizeof(float));
    k_out<<<dim3(T_, M_), DH>>>(ow, ob, fcw, fcb, (float*)d_out);
}

// round 2
// speedup vs baseline: 1.0692x; 1.0692x over previous
#include <cuda_runtime.h>
#include <cuda_bf16.h>
#include <math.h>

#define T_  12
#define M_  2048
#define B_  2
#define N_  1024
#define DIN 64
#define DH  128
#define DT  16
#define DO  32
#define NJC 8          // j-chunks per column (2048/256)
#define CAPC 32        // edge capacity per (column, j-chunk)

// ---------------- device scratch ---------------
__device__ int   g_mdtype;
__device__ int   g_mask[T_ * M_];
__device__ int   g_list[T_ * M_];
__device__ int   g_mcnt[T_];
__device__ int   g_cnt8[T_ * M_ * NJC];
__device__ int   g_col [T_ * M_ * NJC * CAPC];
__device__ float g_nrm [T_ * M_];
__device__ float g_z   [T_ * M_ * DH];
__device__ float g_h   [T_ * M_ * DH];
__device__ float g_Q   [T_ * M_ * DH];   // compacted by list position
__device__ float g_K   [T_ * M_ * DH];
__device__ float g_V   [T_ * M_ * DH];
__device__ float g_agg [T_ * M_ * DH];   // compacted by list position
__device__ float g_qt  [T_ * DH];
__device__ float g_kt  [T_ * DH];
__device__ float g_vt  [T_ * DH];
__device__ float g_wc  [DH * DO];        // o_w @ fc_w
__device__ float g_bc  [DO];             // o_b @ fc_w + fc_b

// ---------------- mask dtype detection ----------------
__global__ void k_detect(const void* p) {
    const int*   wi = (const int*)p;
    const float* wf = (const float*)p;
    int oki = 1, okf = 1;
    for (int r = 0; r < 8; r++) {
        int idx = r * 256 + threadIdx.x;
        int w  = wi[idx];
        float f = wf[idx];
        oki &= (w == 0 || w == 1);
        okf &= (f == 0.0f || f == 1.0f);
    }
    oki = __syncthreads_and(oki);
    okf = __syncthreads_and(okf);
    if (threadIdx.x == 0) g_mdtype = okf ? 2 : (oki ? 1 : 0);
}

__global__ void k_mask(const void* em) {
    int idx = blockIdx.x * 256 + threadIdx.x;
    int t = idx >> 11, m = idx & (M_ - 1);
    int b = m >> 10, n = m & (N_ - 1);
    int src = (b * T_ + t) * N_ + n;
    int dt = g_mdtype;
    int v;
    if (dt == 1)      v = ((const int*)em)[src] != 0;
    else if (dt == 2) v = ((const float*)em)[src] != 0.0f;
    else              v = ((const unsigned char*)em)[src] != 0;
    g_mask[idx] = v;
}

__global__ void __launch_bounds__(1024) k_compact() {
    int t = blockIdx.x, tid = threadIdx.x;
    __shared__ int wsum[32];
    __shared__ int sbase;
    if (tid == 0) sbase = 0;
    __syncthreads();
    for (int half = 0; half < 2; half++) {
        int i = half * 1024 + tid;
        int mv = g_mask[t * M_ + i];
        unsigned b = __ballot_sync(0xffffffffu, mv);
        int lane = tid & 31, wid = tid >> 5;
        if (lane == 0) wsum[wid] = __popc(b);
        __syncthreads();
        int woff = 0;
        for (int w = 0; w < wid; w++) woff += wsum[w];
        if (mv) g_list[t * M_ + sbase + woff + __popc(b & ((1u << lane) - 1u))] = i;
        __syncthreads();
        if (tid == 0) {
            int tot = 0;
            for (int w = 0; w < 32; w++) tot += wsum[w];
            sbase += tot;
        }
        __syncthreads();
    }
    if (tid == 0) g_mcnt[t] = sbase;
}

__global__ void k_edges(const float* __restrict__ A) {
    int t = blockIdx.x, jc = blockIdx.y, ic = blockIdx.z;
    int i = ic * 256 + threadIdx.x;
    __shared__ int mj[256];
    int jbase = jc * 256;
    mj[threadIdx.x] = g_mask[t * M_ + jbase + threadIdx.x];
    __syncthreads();
    int mi = g_mask[t * M_ + i];
    int cnt = 0;
    int* cols = g_col + ((size_t)((t * M_ + i) * NJC + jc)) * CAPC;
    if (mi) {
        const float* Ab = A + (size_t)(t * M_ + jbase) * M_ + i;
        #pragma unroll 4
        for (int jj = 0; jj < 256; jj++) {
            float a = Ab[(size_t)jj * M_];
            if (a != 0.0f && mj[jj] && cnt < CAPC) cols[cnt++] = jbase + jj;
        }
    }
    g_cnt8[(t * M_ + i) * NJC + jc] = cnt;
}

__global__ void k_nrm() {
    int idx = blockIdx.x * 256 + threadIdx.x;
    float nv = 0.0f;
    if (g_mask[idx]) {
        int c = 1;
        #pragma unroll
        for (int jc = 0; jc < NJC; jc++) c += g_cnt8[idx * NJC + jc];
        nv = rsqrtf((float)c);
    }
    g_nrm[idx] = nv;
}

__global__ void k_tbias(const float* __restrict__ tw, const float* __restrict__ tb,
                        const float* __restrict__ qw, const float* __restrict__ qb,
                        const float* __restrict__ kw, const float* __restrict__ kb,
                        const float* __restrict__ vw, const float* __restrict__ vb) {
    int t = blockIdx.x, f = threadIdx.x;
    float tv[DT];
    #pragma unroll
    for (int d = 0; d < DT; d++) tv[d] = sinf((float)t * tw[d] + tb[d]);
    float aq = qb[f], ak = kb[f], av = vb[f];
    #pragma unroll
    for (int d = 0; d < DT; d++) {
        aq += tv[d] * qw[(DH + d) * DH + f];
        ak += tv[d] * kw[(DH + d) * DH + f];
        av += tv[d] * vw[(DH + d) * DH + f];
    }
    g_qt[t * DH + f] = aq;
    g_kt[t * DH + f] = ak;
    g_vt[t * DH + f] = av;
}

// ---------------- combined epilogue weights: wc = ow@fcw, bc = ob@fcw+fcb ----------------
__global__ void k_comb(const float* __restrict__ ow, const float* __restrict__ ob,
                       const float* __restrict__ fcw, const float* __restrict__ fcb) {
    int idx = blockIdx.x * 256 + threadIdx.x;   // 4096 = 128*32
    int d = idx >> 5, f = idx & 31;
    float acc = 0.0f;
    #pragma unroll 8
    for (int e = 0; e < DH; e++) acc += ow[d * DH + e] * fcw[e * DO + f];
    g_wc[idx] = acc;
    if (idx < DO) {
        float b = fcb[idx];
        #pragma unroll 8
        for (int e = 0; e < DH; e++) b += ob[e] * fcw[e * DO + idx];
        g_bc[idx] = b;
    }
}

// ============ tiled GEMM: 64 nodes x 128 features, BK=32, 256 threads =============
// mode 0: src = x (K=64),  out = g_z (by node id), scaled by nrm
// mode 1: src = g_h (K=128), out = g_z (by node id), scaled by nrm
__global__ void __launch_bounds__(256) k_gemm_z(const float* __restrict__ xsrc,
                                                const float* __restrict__ W, int mode) {
    int t = blockIdx.x;
    int mc = g_mcnt[t];
    int mbase = blockIdx.y * 64;
    if (mbase >= mc) return;
    const float* src = (mode == 0) ? xsrc : (const float*)g_h;
    const int K = (mode == 0) ? DIN : DH;

    __shared__ float As[64][36];
    __shared__ float Bs[32][DH];
    __shared__ int   ridx[64];
    __shared__ float rn[64];
    int tid = threadIdx.x;
    if (tid < 64) {
        int lp = mbase + tid;
        int i = g_list[t * M_ + (lp < mc ? lp : mc - 1)];
        ridx[tid] = i;
        rn[tid] = g_nrm[t * M_ + i];
    }

    float acc[4][8];
    #pragma unroll
    for (int i = 0; i < 4; i++)
        #pragma unroll
        for (int j = 0; j < 8; j++) acc[i][j] = 0.0f;
    int ty = tid >> 4, tx = tid & 15;
    int m0 = ty * 4, n0 = tx * 8;

    for (int k0 = 0; k0 < K; k0 += 32) {
        __syncthreads();
        {   // A tile (gathered rows)
            int m = tid >> 3;
            int kk = (tid & 7) * 4;
            #pragma unroll
            for (int p = 0; p < 2; p++) {
                int mm = m + p * 32;
                float4 v = *(const float4*)(src + (size_t)(t * M_ + ridx[mm]) * K + k0 + kk);
                As[mm][kk] = v.x; As[mm][kk + 1] = v.y; As[mm][kk + 2] = v.z; As[mm][kk + 3] = v.w;
            }
        }
        {   // B tile: rows k0..k0+31 of W are contiguous
            float4* Bs4 = (float4*)Bs;
            const float4* W4 = (const float4*)(W + (size_t)k0 * DH);
            #pragma unroll
            for (int p = 0; p < 4; p++) Bs4[tid + p * 256] = W4[tid + p * 256];
        }
        __syncthreads();
        #pragma unroll
        for (int kk = 0; kk < 32; kk++) {
            float a0 = As[m0][kk], a1 = As[m0 + 1][kk], a2 = As[m0 + 2][kk], a3 = As[m0 + 3][kk];
            float4 b0 = *(float4*)&Bs[kk][n0];
            float4 b1 = *(float4*)&Bs[kk][n0 + 4];
            acc[0][0] += a0 * b0.x; acc[0][1] += a0 * b0.y; acc[0][2] += a0 * b0.z; acc[0][3] += a0 * b0.w;
            acc[0][4] += a0 * b1.x; acc[0][5] += a0 * b1.y; acc[0][6] += a0 * b1.z; acc[0][7] += a0 * b1.w;
            acc[1][0] += a1 * b0.x; acc[1][1] += a1 * b0.y; acc[1][2] += a1 * b0.z; acc[1][3] += a1 * b0.w;
            acc[1][4] += a1 * b1.x; acc[1][5] += a1 * b1.y; acc[1][6] += a1 * b1.z; acc[1][7] += a1 * b1.w;
            acc[2][0] += a2 * b0.x; acc[2][1] += a2 * b0.y; acc[2][2] += a2 * b0.z; acc[2][3] += a2 * b0.w;
            acc[2][4] += a2 * b1.x; acc[2][5] += a2 * b1.y; acc[2][6] += a2 * b1.z; acc[2][7] += a2 * b1.w;
            acc[3][0] += a3 * b0.x; acc[3][1] += a3 * b0.y; acc[3][2] += a3 * b0.z; acc[3][3] += a3 * b0.w;
            acc[3][4] += a3 * b1.x; acc[3][5] += a3 * b1.y; acc[3][6] += a3 * b1.z; acc[3][7] += a3 * b1.w;
        }
    }
    #pragma unroll
    for (int i = 0; i < 4; i++) {
        int lp = mbase + m0 + i;
        if (lp < mc) {
            float s = rn[m0 + i];
            float* dst = g_z + (size_t)(t * M_ + ridx[m0 + i]) * DH + n0;
            float4 o0 = {acc[i][0] * s, acc[i][1] * s, acc[i][2] * s, acc[i][3] * s};
            float4 o1 = {acc[i][4] * s, acc[i][5] * s, acc[i][6] * s, acc[i][7] * s};
            *(float4*)dst = o0;
            *(float4*)(dst + 4) = o1;
        }
    }
}

// Q/K/V GEMM: src = g_h (gathered), out compacted by lp, + time bias. blockIdx.z selects weight.
__global__ void __launch_bounds__(256) k_gemm_qkv(const float* __restrict__ qw,
                                                  const float* __restrict__ kw,
                                                  const float* __restrict__ vw) {
    int t = blockIdx.x;
    int mc = g_mcnt[t];
    int mbase = blockIdx.y * 64;
    if (mbase >= mc) return;
    int sel = blockIdx.z;
    const float* W  = (sel == 0) ? qw : (sel == 1) ? kw : vw;
    const float* tb = (sel == 0) ? g_qt : (sel == 1) ? g_kt : g_vt;
    float* out      = (sel == 0) ? g_Q : (sel == 1) ? g_K : g_V;

    __shared__ float As[64][36];
    __shared__ float Bs[32][DH];
    __shared__ int   ridx[64];
    int tid = threadIdx.x;
    if (tid < 64) {
        int lp = mbase + tid;
        ridx[tid] = g_list[t * M_ + (lp < mc ? lp : mc - 1)];
    }
    float acc[4][8];
    #pragma unroll
    for (int i = 0; i < 4; i++)
        #pragma unroll
        for (int j = 0; j < 8; j++) acc[i][j] = 0.0f;
    int ty = tid >> 4, tx = tid & 15;
    int m0 = ty * 4, n0 = tx * 8;

    for (int k0 = 0; k0 < DH; k0 += 32) {
        __syncthreads();
        {
            int m = tid >> 3;
            int kk = (tid & 7) * 4;
            #pragma unroll
            for (int p = 0; p < 2; p++) {
                int mm = m + p * 32;
                float4 v = *(const float4*)(g_h + (size_t)(t * M_ + ridx[mm]) * DH + k0 + kk);
                As[mm][kk] = v.x; As[mm][kk + 1] = v.y; As[mm][kk + 2] = v.z; As[mm][kk + 3] = v.w;
            }
        }
        {
            float4* Bs4 = (float4*)Bs;
            const float4* W4 = (const float4*)(W + (size_t)k0 * DH);
            #pragma unroll
            for (int p = 0; p < 4; p++) Bs4[tid + p * 256] = W4[tid + p * 256];
        }
        __syncthreads();
        #pragma unroll
        for (int kk = 0; kk < 32; kk++) {
            float a0 = As[m0][kk], a1 = As[m0 + 1][kk], a2 = As[m0 + 2][kk], a3 = As[m0 + 3][kk];
            float4 b0 = *(float4*)&Bs[kk][n0];
            float4 b1 = *(float4*)&Bs[kk][n0 + 4];
            acc[0][0] += a0 * b0.x; acc[0][1] += a0 * b0.y; acc[0][2] += a0 * b0.z; acc[0][3] += a0 * b0.w;
            acc[0][4] += a0 * b1.x; acc[0][5] += a0 * b1.y; acc[0][6] += a0 * b1.z; acc[0][7] += a0 * b1.w;
            acc[1][0] += a1 * b0.x; acc[1][1] += a1 * b0.y; acc[1][2] += a1 * b0.z; acc[1][3] += a1 * b0.w;
            acc[1][4] += a1 * b1.x; acc[1][5] += a1 * b1.y; acc[1][6] += a1 * b1.z; acc[1][7] += a1 * b1.w;
            acc[2][0] += a2 * b0.x; acc[2][1] += a2 * b0.y; acc[2][2] += a2 * b0.z; acc[2][3] += a2 * b0.w;
            acc[2][4] += a2 * b1.x; acc[2][5] += a2 * b1.y; acc[2][6] += a2 * b1.z; acc[2][7] += a2 * b1.w;
            acc[3][0] += a3 * b0.x; acc[3][1] += a3 * b0.y; acc[3][2] += a3 * b0.z; acc[3][3] += a3 * b0.w;
            acc[3][4] += a3 * b1.x; acc[3][5] += a3 * b1.y; acc[3][6] += a3 * b1.z; acc[3][7] += a3 * b1.w;
        }
    }
    float4 tb0 = *(const float4*)(tb + t * DH + n0);
    float4 tb1 = *(const float4*)(tb + t * DH + n0 + 4);
    #pragma unroll
    for (int i = 0; i < 4; i++) {
        int lp = mbase + m0 + i;
        if (lp < mc) {
            float* dst = out + (size_t)(t * M_ + lp) * DH + n0;
            float4 o0 = {acc[i][0] + tb0.x, acc[i][1] + tb0.y, acc[i][2] + tb0.z, acc[i][3] + tb0.w};
            float4 o1 = {acc[i][4] + tb1.x, acc[i][5] + tb1.y, acc[i][6] + tb1.z, acc[i][7] + tb1.w};
            *(float4*)dst = o0;
            *(float4*)(dst + 4) = o1;
        }
    }
}

// fused epilogue GEMM: out = agg @ wc + bc, scatter rows to d_out. 64 nodes x 32 cols.
__global__ void __launch_bounds__(256) k_out2(float* __restrict__ out) {
    int t = blockIdx.x;
    int mc = g_mcnt[t];
    int mbase = blockIdx.y * 64;
    if (mbase >= mc) return;
    __shared__ float As[64][36];
    __shared__ float Ws[32][DO];
    __shared__ int   ridx[64];
    int tid = threadIdx.x;
    if (tid < 64) {
        int lp = mbase + tid;
        ridx[tid] = g_list[t * M_ + (lp < mc ? lp : mc - 1)];
    }
    float acc[4][2];
    #pragma unroll
    for (int i = 0; i < 4; i++) { acc[i][0] = 0.0f; acc[i][1] = 0.0f; }
    int ty = tid >> 4, tx = tid & 15;
    int m0 = ty * 4, n0 = tx * 2;

    for (int k0 = 0; k0 < DH; k0 += 32) {
        __syncthreads();
        {
            int m = tid >> 3;
            int kk = (tid & 7) * 4;
            #pragma unroll
            for (int p = 0; p < 2; p++) {
                int mm = m + p * 32;
                int lp = mbase + mm;
                int lpc = (lp < mc ? lp : mc - 1);
                float4 v = *(const float4*)(g_agg + (size_t)(t * M_ + lpc) * DH + k0 + kk);
                As[mm][kk] = v.x; As[mm][kk + 1] = v.y; As[mm][kk + 2] = v.z; As[mm][kk + 3] = v.w;
            }
        }
        {
            float4* Ws4 = (float4*)Ws;
            const float4* W4 = (const float4*)(g_wc + (size_t)k0 * DO);
            Ws4[tid] = W4[tid];
        }
        __syncthreads();
        #pragma unroll
        for (int kk = 0; kk < 32; kk++) {
            float a0 = As[m0][kk], a1 = As[m0 + 1][kk], a2 = As[m0 + 2][kk], a3 = As[m0 + 3][kk];
            float2 b = *(float2*)&Ws[kk][n0];
            acc[0][0] += a0 * b.x; acc[0][1] += a0 * b.y;
            acc[1][0] += a1 * b.x; acc[1][1] += a1 * b.y;
            acc[2][0] += a2 * b.x; acc[2][1] += a2 * b.y;
            acc[3][0] += a3 * b.x; acc[3][1] += a3 * b.y;
        }
    }
    float2 bc = *(const float2*)(g_bc + n0);
    #pragma unroll
    for (int i = 0; i < 4; i++) {
        int lp = mbase + m0 + i;
        if (lp < mc) {
            int node = ridx[m0 + i];
            float2 o = {acc[i][0] + bc.x, acc[i][1] + bc.y};
            *(float2*)(out + ((size_t)node * T_ + t) * DO + n0) = o;
        }
    }
}

// ---------------- sparse aggregation + bias + ReLU ----------------
__global__ void k_spmm(const float* __restrict__ bias) {
    int t = blockIdx.x, lp = blockIdx.y;
    if (lp >= g_mcnt[t]) return;
    int i = g_list[t * M_ + lp];
    int f = threadIdx.x;
    float acc = g_z[(size_t)(t * M_ + i) * DH + f];
    const int* c8 = g_cnt8 + (t * M_ + i) * NJC;
    #pragma unroll
    for (int jc = 0; jc < NJC; jc++) {
        int c = c8[jc];
        const int* cl = g_col + ((size_t)((t * M_ + i) * NJC + jc)) * CAPC;
        for (int e = 0; e < c; e++) {
            int j = cl[e];
            acc += g_z[(size_t)(t * M_ + j) * DH + f];
        }
    }
    g_h[(size_t)(t * M_ + i) * DH + f] =
        fmaxf(g_nrm[t * M_ + i] * acc + bias[f], 0.0f);
}

// ---------------- flash-style attention over masked nodes ----------------
#define QT 32
#define KC 64
extern __shared__ float smattn[];
__global__ void __launch_bounds__(256) k_attn() {
    int t = blockIdx.x;
    int mc = g_mcnt[t];
    int qb = blockIdx.y * QT;
    if (qb >= mc) return;
    float* Qs   = smattn;
    float* Ks   = Qs + QT * DH;
    float* S    = Ks + KC * DH;
    float* rowm = S + QT * KC;
    float* rowl = rowm + QT;
    float* rowsc= rowl + QT;
    int tid = threadIdx.x;
    int nv = min(QT, mc - qb);

    for (int idx = tid; idx < QT * DH; idx += 256) {
        int q = idx >> 7;
        Qs[idx] = (q < nv) ? g_Q[(size_t)(t * M_ + qb + q) * DH + (idx & 127)] : 0.0f;
    }
    if (tid < QT) { rowm[tid] = -1e30f; rowl[tid] = 0.0f; }

    float acc[16];
    #pragma unroll
    for (int j = 0; j < 16; j++) acc[j] = 0.0f;
    int q0 = (tid >> 4) * 2;
    int f0 = (tid & 15) * 8;
    int sk0 = (tid & 15) * 4;
    const float scl = 0.08838834764831845f;

    for (int kb = 0; kb < mc; kb += KC) {
        int kn = min(KC, mc - kb);
        __syncthreads();
        for (int idx = tid; idx < KC * DH; idx += 256) {
            int k = idx >> 7;
            Ks[idx] = (k < kn) ? g_K[(size_t)(t * M_ + kb + k) * DH + (idx & 127)] : 0.0f;
        }
        __syncthreads();
        {
            const float4* Qa = (const float4*)(Qs + q0 * DH);
            const float4* Qb = (const float4*)(Qs + (q0 + 1) * DH);
            const float4* K0 = (const float4*)(Ks + (sk0 + 0) * DH);
            const float4* K1 = (const float4*)(Ks + (sk0 + 1) * DH);
            const float4* K2 = (const float4*)(Ks + (sk0 + 2) * DH);
            const float4* K3 = (const float4*)(Ks + (sk0 + 3) * DH);
            float s00=0,s01=0,s02=0,s03=0,s10=0,s11=0,s12=0,s13=0;
            #pragma unroll 4
            for (int d = 0; d < DH / 4; d++) {
                float4 qa = Qa[d], qc = Qb[d];
                float4 k0 = K0[d], k1 = K1[d], k2 = K2[d], k3 = K3[d];
                s00 += qa.x*k0.x + qa.y*k0.y + qa.z*k0.z + qa.w*k0.w;
                s01 += qa.x*k1.x + qa.y*k1.y + qa.z*k1.z + qa.w*k1.w;
                s02 += qa.x*k2.x + qa.y*k2.y + qa.z*k2.z + qa.w*k2.w;
                s03 += qa.x*k3.x + qa.y*k3.y + qa.z*k3.z + qa.w*k3.w;
                s10 += qc.x*k0.x + qc.y*k0.y + qc.z*k0.z + qc.w*k0.w;
                s11 += qc.x*k1.x + qc.y*k1.y + qc.z*k1.z + qc.w*k1.w;
                s12 += qc.x*k2.x + qc.y*k2.y + qc.z*k2.z + qc.w*k2.w;
                s13 += qc.x*k3.x + qc.y*k3.y + qc.z*k3.z + qc.w*k3.w;
            }
            S[q0*KC + sk0+0] = (sk0+0 < kn) ? s00*scl : -1e30f;
            S[q0*KC + sk0+1] = (sk0+1 < kn) ? s01*scl : -1e30f;
            S[q0*KC + sk0+2] = (sk0+2 < kn) ? s02*scl : -1e30f;
            S[q0*KC + sk0+3] = (sk0+3 < kn) ? s03*scl : -1e30f;
            S[(q0+1)*KC + sk0+0] = (sk0+0 < kn) ? s10*scl : -1e30f;
            S[(q0+1)*KC + sk0+1] = (sk0+1 < kn) ? s11*scl : -1e30f;
            S[(q0+1)*KC + sk0+2] = (sk0+2 < kn) ? s12*scl : -1e30f;
            S[(q0+1)*KC + sk0+3] = (sk0+3 < kn) ? s13*scl : -1e30f;
        }
        __syncthreads();
        {
            int w = tid >> 5, lane = tid & 31;
            int row = w * 4 + (lane >> 3);
            int l8 = lane & 7;
            float mloc = -1e30f;
            #pragma unroll
            for (int k = l8; k < KC; k += 8) mloc = fmaxf(mloc, S[row*KC + k]);
            #pragma unroll
            for (int o = 4; o >= 1; o >>= 1)
                mloc = fmaxf(mloc, __shfl_xor_sync(0xffffffffu, mloc, o));
            float oldm = rowm[row];
            float newm = fmaxf(oldm, mloc);
            float ssum = 0.0f;
            #pragma unroll
            for (int k = l8; k < KC; k += 8) {
                float p = __expf(S[row*KC + k] - newm);
                S[row*KC + k] = p;
                ssum += p;
            }
            #pragma unroll
            for (int o = 4; o >= 1; o >>= 1)
                ssum += __shfl_xor_sync(0xffffffffu, ssum, o);
            if (l8 == 0) {
                float sc = __expf(oldm - newm);
                rowsc[row] = sc;
                rowl[row] = rowl[row] * sc + ssum;
                rowm[row] = newm;
            }
        }
        __syncthreads();
        {
            float sc0 = rowsc[q0], sc1 = rowsc[q0 + 1];
            #pragma unroll
            for (int j = 0; j < 8; j++)  acc[j]     *= sc0;
            #pragma unroll
            for (int j = 0; j < 8; j++)  acc[8 + j] *= sc1;
        }
        for (int idx = tid; idx < KC * DH; idx += 256) {
            int k = idx >> 7;
            Ks[idx] = (k < kn) ? g_V[(size_t)(t * M_ + kb + k) * DH + (idx & 127)] : 0.0f;
        }
        __syncthreads();
        {
            const float* Sq0 = S + q0 * KC;
            const float* Sq1 = S + (q0 + 1) * KC;
            for (int k = 0; k < kn; k++) {
                float p0 = Sq0[k], p1 = Sq1[k];
                const float4* V4 = (const float4*)(Ks + k * DH + f0);
                float4 va = V4[0], vb = V4[1];
                acc[0] += p0*va.x; acc[1] += p0*va.y; acc[2] += p0*va.z; acc[3] += p0*va.w;
                acc[4] += p0*vb.x; acc[5] += p0*vb.y; acc[6] += p0*vb.z; acc[7] += p0*vb.w;
                acc[8] += p1*va.x; acc[9] += p1*va.y; acc[10]+= p1*va.z; acc[11]+= p1*va.w;
                acc[12]+= p1*vb.x; acc[13]+= p1*vb.y; acc[14]+= p1*vb.z; acc[15]+= p1*vb.w;
            }
        }
    }
    __syncthreads();
    if (q0 < nv) {
        float inv = 1.0f / rowl[q0];
        #pragma unroll
        for (int j = 0; j < 8; j++)
            g_agg[(size_t)(t * M_ + qb + q0) * DH + f0 + j] = acc[j] * inv;
    }
    if (q0 + 1 < nv) {
        float inv = 1.0f / rowl[q0 + 1];
        #pragma unroll
        for (int j = 0; j < 8; j++)
            g_agg[(size_t)(t * M_ + qb + q0 + 1) * DH + f0 + j] = acc[8 + j] * inv;
    }
}

// ---------------- launch ----------------
extern "C" void kernel_launch(void* const* d_in, const int* in_sizes, int n_in,
                              void* d_out, int out_size) {
    const float* x   = (const float*)d_in[0];
    const float* A   = (const float*)d_in[1];
    const void*  em  = d_in[2];
    const float* w1  = (const float*)d_in[3];
    const float* b1  = (const float*)d_in[4];
    const float* w2  = (const float*)d_in[5];
    const float* b2  = (const float*)d_in[6];
    const float* tw  = (const float*)d_in[7];
    const float* tb  = (const float*)d_in[8];
    const float* qw  = (const float*)d_in[9];
    const float* qb  = (const float*)d_in[10];
    const float* kw  = (const float*)d_in[11];
    const float* kb  = (const float*)d_in[12];
    const float* vw  = (const float*)d_in[13];
    const float* vb  = (const float*)d_in[14];
    const float* ow  = (const float*)d_in[15];
    const float* ob  = (const float*)d_in[16];
    const float* fcw = (const float*)d_in[17];
    const float* fcb = (const float*)d_in[18];

    static bool attr_set = false;
    const int ATTN_SMEM = (QT * DH + KC * DH + QT * KC + 3 * QT) * 4;
    if (!attr_set) {
        cudaFuncSetAttribute(k_attn, cudaFuncAttributeMaxDynamicSharedMemorySize, ATTN_SMEM);
        attr_set = true;
    }

    k_detect<<<1, 256>>>(em);
    k_mask<<<(T_ * M_) / 256, 256>>>(em);
    k_compact<<<T_, 1024>>>();
    k_edges<<<dim3(T_, NJC, M_ / 256), 256>>>(A);
    k_nrm<<<(T_ * M_) / 256, 256>>>();
    k_tbias<<<T_, DH>>>(tw, tb, qw, qb, kw, kb, vw, vb);
    k_comb<<<16, 256>>>(ow, ob, fcw, fcb);
    k_gemm_z<<<dim3(T_, M_ / 64), 256>>>(x, w1, 0);
    k_spmm<<<dim3(T_, M_), DH>>>(b1);
    k_gemm_z<<<dim3(T_, M_ / 64), 256>>>(nullptr, w2, 1);
    k_spmm<<<dim3(T_, M_), DH>>>(b2);
    k_gemm_qkv<<<dim3(T_, M_ / 64, 3), 256>>>(qw, kw, vw);
    k_attn<<<dim3(T_, M_ / QT), 256, ATTN_SMEM>>>();
    cudaMemsetAsync(d_out, 0, (size_t)out_size * sizeof(float));
    k_out2<<<dim3(T_, M_ / 64), 256>>>((float*)d_out);
}

// round 3
// speedup vs baseline: 2.7804x; 2.6005x over previous
#include <cuda_runtime.h>
#include <cuda_bf16.h>
#include <math.h>

#define T_  12
#define M_  2048
#define B_  2
#define N_  1024
#define DIN 64
#define DH  128
#define DT  16
#define DO  32
#define NJC 8
#define CAPC 32

// ---------------- device scratch ---------------
__device__ int   g_mdtype;
__device__ int   g_mask[T_ * M_];
__device__ int   g_list[T_ * M_];
__device__ int   g_mcnt[T_];
__device__ int   g_cnt8[T_ * M_ * NJC];
__device__ int   g_col [T_ * M_ * NJC * CAPC];
__device__ float g_nrm [T_ * M_];
__device__ float g_z   [T_ * M_ * DH];
__device__ float g_h   [T_ * M_ * DH];
__device__ float g_Q   [T_ * M_ * DH];
__device__ float g_K   [T_ * M_ * DH];
__device__ float g_V   [T_ * M_ * DH];
__device__ float g_agg [T_ * M_ * DH];
__device__ float g_qt  [T_ * DH];
__device__ float g_kt  [T_ * DH];
__device__ float g_vt  [T_ * DH];
__device__ float g_wc  [DH * DO];
__device__ float g_bc  [DO];

// ---------------- mask dtype detection ----------------
__global__ void k_detect(const void* p) {
    const int*   wi = (const int*)p;
    const float* wf = (const float*)p;
    int oki = 1, okf = 1;
    for (int r = 0; r < 8; r++) {
        int idx = r * 256 + threadIdx.x;
        int w  = wi[idx];
        float f = wf[idx];
        oki &= (w == 0 || w == 1);
        okf &= (f == 0.0f || f == 1.0f);
    }
    oki = __syncthreads_and(oki);
    okf = __syncthreads_and(okf);
    if (threadIdx.x == 0) g_mdtype = okf ? 2 : (oki ? 1 : 0);
}

__global__ void k_mask(const void* em) {
    int idx = blockIdx.x * 256 + threadIdx.x;
    int t = idx >> 11, m = idx & (M_ - 1);
    int b = m >> 10, n = m & (N_ - 1);
    int src = (b * T_ + t) * N_ + n;
    int dt = g_mdtype;
    int v;
    if (dt == 1)      v = ((const int*)em)[src] != 0;
    else if (dt == 2) v = ((const float*)em)[src] != 0.0f;
    else              v = ((const unsigned char*)em)[src] != 0;
    g_mask[idx] = v;
}

__global__ void __launch_bounds__(1024) k_compact() {
    int t = blockIdx.x, tid = threadIdx.x;
    __shared__ int wsum[32];
    __shared__ int sbase;
    if (tid == 0) sbase = 0;
    __syncthreads();
    for (int half = 0; half < 2; half++) {
        int i = half * 1024 + tid;
        int mv = g_mask[t * M_ + i];
        unsigned b = __ballot_sync(0xffffffffu, mv);
        int lane = tid & 31, wid = tid >> 5;
        if (lane == 0) wsum[wid] = __popc(b);
        __syncthreads();
        int woff = 0;
        for (int w = 0; w < wid; w++) woff += wsum[w];
        if (mv) g_list[t * M_ + sbase + woff + __popc(b & ((1u << lane) - 1u))] = i;
        __syncthreads();
        if (tid == 0) {
            int tot = 0;
            for (int w = 0; w < 32; w++) tot += wsum[w];
            sbase += tot;
        }
        __syncthreads();
    }
    if (tid == 0) g_mcnt[t] = sbase;
}

__global__ void k_edges(const float* __restrict__ A) {
    int t = blockIdx.x, jc = blockIdx.y, ic = blockIdx.z;
    int i = ic * 256 + threadIdx.x;
    __shared__ int mj[256];
    int jbase = jc * 256;
    mj[threadIdx.x] = g_mask[t * M_ + jbase + threadIdx.x];
    __syncthreads();
    int mi = g_mask[t * M_ + i];
    int cnt = 0;
    int* cols = g_col + ((size_t)((t * M_ + i) * NJC + jc)) * CAPC;
    if (mi) {
        const float* Ab = A + (size_t)(t * M_ + jbase) * M_ + i;
        #pragma unroll 8
        for (int jj = 0; jj < 256; jj++) {
            float a = Ab[(size_t)jj * M_];
            if (a != 0.0f && mj[jj] && cnt < CAPC) cols[cnt++] = jbase + jj;
        }
    }
    g_cnt8[(t * M_ + i) * NJC + jc] = cnt;
}

__global__ void k_nrm() {
    int idx = blockIdx.x * 256 + threadIdx.x;
    float nv = 0.0f;
    if (g_mask[idx]) {
        int c = 1;
        #pragma unroll
        for (int jc = 0; jc < NJC; jc++) c += g_cnt8[idx * NJC + jc];
        nv = rsqrtf((float)c);
    }
    g_nrm[idx] = nv;
}

__global__ void k_tbias(const float* __restrict__ tw, const float* __restrict__ tb,
                        const float* __restrict__ qw, const float* __restrict__ qb,
                        const float* __restrict__ kw, const float* __restrict__ kb,
                        const float* __restrict__ vw, const float* __restrict__ vb) {
    int t = blockIdx.x, f = threadIdx.x;
    float tv[DT];
    #pragma unroll
    for (int d = 0; d < DT; d++) tv[d] = sinf((float)t * tw[d] + tb[d]);
    float aq = qb[f], ak = kb[f], av = vb[f];
    #pragma unroll
    for (int d = 0; d < DT; d++) {
        aq += tv[d] * qw[(DH + d) * DH + f];
        ak += tv[d] * kw[(DH + d) * DH + f];
        av += tv[d] * vw[(DH + d) * DH + f];
    }
    g_qt[t * DH + f] = aq;
    g_kt[t * DH + f] = ak;
    g_vt[t * DH + f] = av;
}

__global__ void k_comb(const float* __restrict__ ow, const float* __restrict__ ob,
                       const float* __restrict__ fcw, const float* __restrict__ fcb) {
    int idx = blockIdx.x * 256 + threadIdx.x;
    int d = idx >> 5, f = idx & 31;
    float acc = 0.0f;
    #pragma unroll 8
    for (int e = 0; e < DH; e++) acc += ow[d * DH + e] * fcw[e * DO + f];
    g_wc[idx] = acc;
    if (idx < DO) {
        float b = fcb[idx];
        #pragma unroll 8
        for (int e = 0; e < DH; e++) b += ob[e] * fcw[e * DO + idx];
        g_bc[idx] = b;
    }
}

// ============ tiled GEMM: 64 nodes x 128 features, BK=32, 256 threads =============
__global__ void __launch_bounds__(256) k_gemm_z(const float* __restrict__ xsrc,
                                                const float* __restrict__ W, int mode) {
    int t = blockIdx.x;
    int mc = g_mcnt[t];
    int mbase = blockIdx.y * 64;
    if (mbase >= mc) return;
    const float* src = (mode == 0) ? xsrc : (const float*)g_h;
    const int K = (mode == 0) ? DIN : DH;

    __shared__ float As[64][36];
    __shared__ float Bs[32][DH];
    __shared__ int   ridx[64];
    __shared__ float rn[64];
    int tid = threadIdx.x;
    if (tid < 64) {
        int lp = mbase + tid;
        int i = g_list[t * M_ + (lp < mc ? lp : mc - 1)];
        ridx[tid] = i;
        rn[tid] = g_nrm[t * M_ + i];
    }

    float acc[4][8];
    #pragma unroll
    for (int i = 0; i < 4; i++)
        #pragma unroll
        for (int j = 0; j < 8; j++) acc[i][j] = 0.0f;
    int ty = tid >> 4, tx = tid & 15;
    int m0 = ty * 4, n0 = tx * 8;

    for (int k0 = 0; k0 < K; k0 += 32) {
        __syncthreads();
        {
            int m = tid >> 3;
            int kk = (tid & 7) * 4;
            #pragma unroll
            for (int p = 0; p < 2; p++) {
                int mm = m + p * 32;
                float4 v = *(const float4*)(src + (size_t)(t * M_ + ridx[mm]) * K + k0 + kk);
                As[mm][kk] = v.x; As[mm][kk + 1] = v.y; As[mm][kk + 2] = v.z; As[mm][kk + 3] = v.w;
            }
        }
        {
            float4* Bs4 = (float4*)Bs;
            const float4* W4 = (const float4*)(W + (size_t)k0 * DH);
            #pragma unroll
            for (int p = 0; p < 4; p++) Bs4[tid + p * 256] = W4[tid + p * 256];
        }
        __syncthreads();
        #pragma unroll
        for (int kk = 0; kk < 32; kk++) {
            float a0 = As[m0][kk], a1 = As[m0 + 1][kk], a2 = As[m0 + 2][kk], a3 = As[m0 + 3][kk];
            float4 b0 = *(float4*)&Bs[kk][n0];
            float4 b1 = *(float4*)&Bs[kk][n0 + 4];
            acc[0][0] += a0 * b0.x; acc[0][1] += a0 * b0.y; acc[0][2] += a0 * b0.z; acc[0][3] += a0 * b0.w;
            acc[0][4] += a0 * b1.x; acc[0][5] += a0 * b1.y; acc[0][6] += a0 * b1.z; acc[0][7] += a0 * b1.w;
            acc[1][0] += a1 * b0.x; acc[1][1] += a1 * b0.y; acc[1][2] += a1 * b0.z; acc[1][3] += a1 * b0.w;
            acc[1][4] += a1 * b1.x; acc[1][5] += a1 * b1.y; acc[1][6] += a1 * b1.z; acc[1][7] += a1 * b1.w;
            acc[2][0] += a2 * b0.x; acc[2][1] += a2 * b0.y; acc[2][2] += a2 * b0.z; acc[2][3] += a2 * b0.w;
            acc[2][4] += a2 * b1.x; acc[2][5] += a2 * b1.y; acc[2][6] += a2 * b1.z; acc[2][7] += a2 * b1.w;
            acc[3][0] += a3 * b0.x; acc[3][1] += a3 * b0.y; acc[3][2] += a3 * b0.z; acc[3][3] += a3 * b0.w;
            acc[3][4] += a3 * b1.x; acc[3][5] += a3 * b1.y; acc[3][6] += a3 * b1.z; acc[3][7] += a3 * b1.w;
        }
    }
    #pragma unroll
    for (int i = 0; i < 4; i++) {
        int lp = mbase + m0 + i;
        if (lp < mc) {
            float s = rn[m0 + i];
            float* dst = g_z + (size_t)(t * M_ + ridx[m0 + i]) * DH + n0;
            float4 o0 = {acc[i][0] * s, acc[i][1] * s, acc[i][2] * s, acc[i][3] * s};
            float4 o1 = {acc[i][4] * s, acc[i][5] * s, acc[i][6] * s, acc[i][7] * s};
            *(float4*)dst = o0;
            *(float4*)(dst + 4) = o1;
        }
    }
}

__global__ void __launch_bounds__(256) k_gemm_qkv(const float* __restrict__ qw,
                                                  const float* __restrict__ kw,
                                                  const float* __restrict__ vw) {
    int t = blockIdx.x;
    int mc = g_mcnt[t];
    int mbase = blockIdx.y * 64;
    if (mbase >= mc) return;
    int sel = blockIdx.z;
    const float* W  = (sel == 0) ? qw : (sel == 1) ? kw : vw;
    const float* tb = (sel == 0) ? g_qt : (sel == 1) ? g_kt : g_vt;
    float* out      = (sel == 0) ? g_Q : (sel == 1) ? g_K : g_V;

    __shared__ float As[64][36];
    __shared__ float Bs[32][DH];
    __shared__ int   ridx[64];
    int tid = threadIdx.x;
    if (tid < 64) {
        int lp = mbase + tid;
        ridx[tid] = g_list[t * M_ + (lp < mc ? lp : mc - 1)];
    }
    float acc[4][8];
    #pragma unroll
    for (int i = 0; i < 4; i++)
        #pragma unroll
        for (int j = 0; j < 8; j++) acc[i][j] = 0.0f;
    int ty = tid >> 4, tx = tid & 15;
    int m0 = ty * 4, n0 = tx * 8;

    for (int k0 = 0; k0 < DH; k0 += 32) {
        __syncthreads();
        {
            int m = tid >> 3;
            int kk = (tid & 7) * 4;
            #pragma unroll
            for (int p = 0; p < 2; p++) {
                int mm = m + p * 32;
                float4 v = *(const float4*)(g_h + (size_t)(t * M_ + ridx[mm]) * DH + k0 + kk);
                As[mm][kk] = v.x; As[mm][kk + 1] = v.y; As[mm][kk + 2] = v.z; As[mm][kk + 3] = v.w;
            }
        }
        {
            float4* Bs4 = (float4*)Bs;
            const float4* W4 = (const float4*)(W + (size_t)k0 * DH);
            #pragma unroll
            for (int p = 0; p < 4; p++) Bs4[tid + p * 256] = W4[tid + p * 256];
        }
        __syncthreads();
        #pragma unroll
        for (int kk = 0; kk < 32; kk++) {
            float a0 = As[m0][kk], a1 = As[m0 + 1][kk], a2 = As[m0 + 2][kk], a3 = As[m0 + 3][kk];
            float4 b0 = *(float4*)&Bs[kk][n0];
            float4 b1 = *(float4*)&Bs[kk][n0 + 4];
            acc[0][0] += a0 * b0.x; acc[0][1] += a0 * b0.y; acc[0][2] += a0 * b0.z; acc[0][3] += a0 * b0.w;
            acc[0][4] += a0 * b1.x; acc[0][5] += a0 * b1.y; acc[0][6] += a0 * b1.z; acc[0][7] += a0 * b1.w;
            acc[1][0] += a1 * b0.x; acc[1][1] += a1 * b0.y; acc[1][2] += a1 * b0.z; acc[1][3] += a1 * b0.w;
            acc[1][4] += a1 * b1.x; acc[1][5] += a1 * b1.y; acc[1][6] += a1 * b1.z; acc[1][7] += a1 * b1.w;
            acc[2][0] += a2 * b0.x; acc[2][1] += a2 * b0.y; acc[2][2] += a2 * b0.z; acc[2][3] += a2 * b0.w;
            acc[2][4] += a2 * b1.x; acc[2][5] += a2 * b1.y; acc[2][6] += a2 * b1.z; acc[2][7] += a2 * b1.w;
            acc[3][0] += a3 * b0.x; acc[3][1] += a3 * b0.y; acc[3][2] += a3 * b0.z; acc[3][3] += a3 * b0.w;
            acc[3][4] += a3 * b1.x; acc[3][5] += a3 * b1.y; acc[3][6] += a3 * b1.z; acc[3][7] += a3 * b1.w;
        }
    }
    float4 tb0 = *(const float4*)(tb + t * DH + n0);
    float4 tb1 = *(const float4*)(tb + t * DH + n0 + 4);
    #pragma unroll
    for (int i = 0; i < 4; i++) {
        int lp = mbase + m0 + i;
        if (lp < mc) {
            float* dst = out + (size_t)(t * M_ + lp) * DH + n0;
            float4 o0 = {acc[i][0] + tb0.x, acc[i][1] + tb0.y, acc[i][2] + tb0.z, acc[i][3] + tb0.w};
            float4 o1 = {acc[i][4] + tb1.x, acc[i][5] + tb1.y, acc[i][6] + tb1.z, acc[i][7] + tb1.w};
            *(float4*)dst = o0;
            *(float4*)(dst + 4) = o1;
        }
    }
}

__global__ void __launch_bounds__(256) k_out2(float* __restrict__ out) {
    int t = blockIdx.x;
    int mc = g_mcnt[t];
    int mbase = blockIdx.y * 64;
    if (mbase >= mc) return;
    __shared__ float As[64][36];
    __shared__ float Ws[32][DO];
    __shared__ int   ridx[64];
    int tid = threadIdx.x;
    if (tid < 64) {
        int lp = mbase + tid;
        ridx[tid] = g_list[t * M_ + (lp < mc ? lp : mc - 1)];
    }
    float acc[4][2];
    #pragma unroll
    for (int i = 0; i < 4; i++) { acc[i][0] = 0.0f; acc[i][1] = 0.0f; }
    int ty = tid >> 4, tx = tid & 15;
    int m0 = ty * 4, n0 = tx * 2;

    for (int k0 = 0; k0 < DH; k0 += 32) {
        __syncthreads();
        {
            int m = tid >> 3;
            int kk = (tid & 7) * 4;
            #pragma unroll
            for (int p = 0; p < 2; p++) {
                int mm = m + p * 32;
                int lp = mbase + mm;
                int lpc = (lp < mc ? lp : mc - 1);
                float4 v = *(const float4*)(g_agg + (size_t)(t * M_ + lpc) * DH + k0 + kk);
                As[mm][kk] = v.x; As[mm][kk + 1] = v.y; As[mm][kk + 2] = v.z; As[mm][kk + 3] = v.w;
            }
        }
        {
            float4* Ws4 = (float4*)Ws;
            const float4* W4 = (const float4*)(g_wc + (size_t)k0 * DO);
            Ws4[tid] = W4[tid];
        }
        __syncthreads();
        #pragma unroll
        for (int kk = 0; kk < 32; kk++) {
            float a0 = As[m0][kk], a1 = As[m0 + 1][kk], a2 = As[m0 + 2][kk], a3 = As[m0 + 3][kk];
            float2 b = *(float2*)&Ws[kk][n0];
            acc[0][0] += a0 * b.x; acc[0][1] += a0 * b.y;
            acc[1][0] += a1 * b.x; acc[1][1] += a1 * b.y;
            acc[2][0] += a2 * b.x; acc[2][1] += a2 * b.y;
            acc[3][0] += a3 * b.x; acc[3][1] += a3 * b.y;
        }
    }
    float2 bc = *(const float2*)(g_bc + n0);
    #pragma unroll
    for (int i = 0; i < 4; i++) {
        int lp = mbase + m0 + i;
        if (lp < mc) {
            int node = ridx[m0 + i];
            float2 o = {acc[i][0] + bc.x, acc[i][1] + bc.y};
            *(float2*)(out + ((size_t)node * T_ + t) * DO + n0) = o;
        }
    }
}

// ---------------- sparse aggregation + bias + ReLU ----------------
__global__ void k_spmm(const float* __restrict__ bias) {
    int t = blockIdx.x, lp = blockIdx.y;
    if (lp >= g_mcnt[t]) return;
    int i = g_list[t * M_ + lp];
    int f = threadIdx.x;
    float acc = g_z[(size_t)(t * M_ + i) * DH + f];
    const int* c8 = g_cnt8 + (t * M_ + i) * NJC;
    #pragma unroll
    for (int jc = 0; jc < NJC; jc++) {
        int c = c8[jc];
        const int* cl = g_col + ((size_t)((t * M_ + i) * NJC + jc)) * CAPC;
        for (int e = 0; e < c; e++) {
            int j = cl[e];
            acc += g_z[(size_t)(t * M_ + j) * DH + f];
        }
    }
    g_h[(size_t)(t * M_ + i) * DH + f] =
        fmaxf(g_nrm[t * M_ + i] * acc + bias[f], 0.0f);
}

// ---------------- flash-style attention, bank-conflict-free layout ----------------
#define QT 32
#define KC 64
#define KSTR 132      // padded K/V row stride (floats): 528B -> 2-phase optimal reads
#define SSTR 68       // padded score row stride
extern __shared__ float smattn[];
__global__ void __launch_bounds__(256) k_attn() {
    int t = blockIdx.x;
    int mc = g_mcnt[t];
    int qb = blockIdx.y * QT;
    if (qb >= mc) return;
    float* Qs   = smattn;                   // QT*DH
    float* Ks   = Qs + QT * DH;             // KC*KSTR (reused for V)
    float* S    = Ks + KC * KSTR;           // QT*SSTR
    float* rowm = S + QT * SSTR;
    float* rowl = rowm + QT;
    float* rowsc= rowl + QT;
    int tid = threadIdx.x;
    int nv = min(QT, mc - qb);

    // Q fill (float4)
    #pragma unroll
    for (int p = 0; p < 4; p++) {
        int idx4 = tid + p * 256;           // over QT*DH/4 = 1024
        int q = idx4 >> 5, d4 = (idx4 & 31) * 4;
        float4 v = {0.f, 0.f, 0.f, 0.f};
        if (q < nv) v = *(const float4*)(g_Q + (size_t)(t * M_ + qb + q) * DH + d4);
        *(float4*)(Qs + q * DH + d4) = v;
    }
    if (tid < QT) { rowm[tid] = -1e30f; rowl[tid] = 0.0f; }

    float acc[16];
    #pragma unroll
    for (int j = 0; j < 16; j++) acc[j] = 0.0f;
    int q0 = (tid >> 4) * 2;
    int tx = tid & 15;
    const float scl = 0.08838834764831845f;

    for (int kb = 0; kb < mc; kb += KC) {
        int kn = min(KC, mc - kb);
        __syncthreads();
        // K fill (float4, padded rows)
        #pragma unroll
        for (int p = 0; p < 8; p++) {
            int idx4 = tid + p * 256;        // over KC*DH/4 = 2048
            int k = idx4 >> 5, d4 = (idx4 & 31) * 4;
            float4 v = {0.f, 0.f, 0.f, 0.f};
            if (k < kn) v = *(const float4*)(g_K + (size_t)(t * M_ + kb + k) * DH + d4);
            *(float4*)(Ks + k * KSTR + d4) = v;
        }
        __syncthreads();
        // scores: 2q x 4k, k rows {tx, tx+16, tx+32, tx+48} -> conflict-free
        {
            const float4* Qa = (const float4*)(Qs + q0 * DH);
            const float4* Qb = (const float4*)(Qs + (q0 + 1) * DH);
            const float4* K0 = (const float4*)(Ks + (tx     ) * KSTR);
            const float4* K1 = (const float4*)(Ks + (tx + 16) * KSTR);
            const float4* K2 = (const float4*)(Ks + (tx + 32) * KSTR);
            const float4* K3 = (const float4*)(Ks + (tx + 48) * KSTR);
            float s00=0,s01=0,s02=0,s03=0,s10=0,s11=0,s12=0,s13=0;
            #pragma unroll 4
            for (int d = 0; d < DH / 4; d++) {
                float4 qa = Qa[d], qc = Qb[d];
                float4 k0 = K0[d], k1 = K1[d], k2 = K2[d], k3 = K3[d];
                s00 += qa.x*k0.x + qa.y*k0.y + qa.z*k0.z + qa.w*k0.w;
                s01 += qa.x*k1.x + qa.y*k1.y + qa.z*k1.z + qa.w*k1.w;
                s02 += qa.x*k2.x + qa.y*k2.y + qa.z*k2.z + qa.w*k2.w;
                s03 += qa.x*k3.x + qa.y*k3.y + qa.z*k3.z + qa.w*k3.w;
                s10 += qc.x*k0.x + qc.y*k0.y + qc.z*k0.z + qc.w*k0.w;
                s11 += qc.x*k1.x + qc.y*k1.y + qc.z*k1.z + qc.w*k1.w;
                s12 += qc.x*k2.x + qc.y*k2.y + qc.z*k2.z + qc.w*k2.w;
                s13 += qc.x*k3.x + qc.y*k3.y + qc.z*k3.z + qc.w*k3.w;
            }
            float* S0 = S + q0 * SSTR;
            float* S1 = S0 + SSTR;
            S0[tx     ] = (tx      < kn) ? s00 * scl : -1e30f;
            S0[tx + 16] = (tx + 16 < kn) ? s01 * scl : -1e30f;
            S0[tx + 32] = (tx + 32 < kn) ? s02 * scl : -1e30f;
            S0[tx + 48] = (tx + 48 < kn) ? s03 * scl : -1e30f;
            S1[tx     ] = (tx      < kn) ? s10 * scl : -1e30f;
            S1[tx + 16] = (tx + 16 < kn) ? s11 * scl : -1e30f;
            S1[tx + 32] = (tx + 32 < kn) ? s12 * scl : -1e30f;
            S1[tx + 48] = (tx + 48 < kn) ? s13 * scl : -1e30f;
        }
        __syncthreads();
        // online softmax: warp w -> rows 4w..4w+3, 8 lanes per row
        {
            int w = tid >> 5, lane = tid & 31;
            int row = w * 4 + (lane >> 3);
            int l8 = lane & 7;
            float* Sr = S + row * SSTR;
            float mloc = -1e30f;
            #pragma unroll
            for (int k = l8; k < KC; k += 8) mloc = fmaxf(mloc, Sr[k]);
            #pragma unroll
            for (int o = 4; o >= 1; o >>= 1)
                mloc = fmaxf(mloc, __shfl_xor_sync(0xffffffffu, mloc, o));
            float oldm = rowm[row];
            float newm = fmaxf(oldm, mloc);
            float ssum = 0.0f;
            #pragma unroll
            for (int k = l8; k < KC; k += 8) {
                float p = __expf(Sr[k] - newm);
                Sr[k] = p;
                ssum += p;
            }
            #pragma unroll
            for (int o = 4; o >= 1; o >>= 1)
                ssum += __shfl_xor_sync(0xffffffffu, ssum, o);
            if (l8 == 0) {
                float sc = __expf(oldm - newm);
                rowsc[row] = sc;
                rowl[row] = rowl[row] * sc + ssum;
                rowm[row] = newm;
            }
        }
        __syncthreads();
        {
            float sc0 = rowsc[q0], sc1 = rowsc[q0 + 1];
            #pragma unroll
            for (int j = 0; j < 8; j++)  acc[j]     *= sc0;
            #pragma unroll
            for (int j = 0; j < 8; j++)  acc[8 + j] *= sc1;
        }
        // V fill (reuses Ks)
        #pragma unroll
        for (int p = 0; p < 8; p++) {
            int idx4 = tid + p * 256;
            int k = idx4 >> 5, d4 = (idx4 & 31) * 4;
            float4 v = {0.f, 0.f, 0.f, 0.f};
            if (k < kn) v = *(const float4*)(g_V + (size_t)(t * M_ + kb + k) * DH + d4);
            *(float4*)(Ks + k * KSTR + d4) = v;
        }
        __syncthreads();
        // P @ V : f chunks {16*tx, 256+16*tx} bytes -> conflict-free
        {
            const float* Sq0 = S + q0 * SSTR;
            const float* Sq1 = Sq0 + SSTR;
            for (int k = 0; k < kn; k++) {
                float p0 = Sq0[k], p1 = Sq1[k];
                const float* Vr = Ks + k * KSTR;
                float4 va = *(const float4*)(Vr + 4 * tx);
                float4 vb = *(const float4*)(Vr + 64 + 4 * tx);
                acc[0] += p0*va.x; acc[1] += p0*va.y; acc[2] += p0*va.z; acc[3] += p0*va.w;
                acc[4] += p0*vb.x; acc[5] += p0*vb.y; acc[6] += p0*vb.z; acc[7] += p0*vb.w;
                acc[8] += p1*va.x; acc[9] += p1*va.y; acc[10]+= p1*va.z; acc[11]+= p1*va.w;
                acc[12]+= p1*vb.x; acc[13]+= p1*vb.y; acc[14]+= p1*vb.z; acc[15]+= p1*vb.w;
            }
        }
    }
    __syncthreads();
    if (q0 < nv) {
        float inv = 1.0f / rowl[q0];
        float* dst = g_agg + (size_t)(t * M_ + qb + q0) * DH;
        float4 o0 = {acc[0]*inv, acc[1]*inv, acc[2]*inv, acc[3]*inv};
        float4 o1 = {acc[4]*inv, acc[5]*inv, acc[6]*inv, acc[7]*inv};
        *(float4*)(dst + 4 * tx) = o0;
        *(float4*)(dst + 64 + 4 * tx) = o1;
    }
    if (q0 + 1 < nv) {
        float inv = 1.0f / rowl[q0 + 1];
        float* dst = g_agg + (size_t)(t * M_ + qb + q0 + 1) * DH;
        float4 o0 = {acc[8]*inv, acc[9]*inv, acc[10]*inv, acc[11]*inv};
        float4 o1 = {acc[12]*inv, acc[13]*inv, acc[14]*inv, acc[15]*inv};
        *(float4*)(dst + 4 * tx) = o0;
        *(float4*)(dst + 64 + 4 * tx) = o1;
    }
}

// ---------------- launch ----------------
extern "C" void kernel_launch(void* const* d_in, const int* in_sizes, int n_in,
                              void* d_out, int out_size) {
    const float* x   = (const float*)d_in[0];
    const float* A   = (const float*)d_in[1];
    const void*  em  = d_in[2];
    const float* w1  = (const float*)d_in[3];
    const float* b1  = (const float*)d_in[4];
    const float* w2  = (const float*)d_in[5];
    const float* b2  = (const float*)d_in[6];
    const float* tw  = (const float*)d_in[7];
    const float* tb  = (const float*)d_in[8];
    const float* qw  = (const float*)d_in[9];
    const float* qb  = (const float*)d_in[10];
    const float* kw  = (const float*)d_in[11];
    const float* kb  = (const float*)d_in[12];
    const float* vw  = (const float*)d_in[13];
    const float* vb  = (const float*)d_in[14];
    const float* ow  = (const float*)d_in[15];
    const float* ob  = (const float*)d_in[16];
    const float* fcw = (const float*)d_in[17];
    const float* fcb = (const float*)d_in[18];

    static bool attr_set = false;
    const int ATTN_SMEM = (QT * DH + KC * KSTR + QT * SSTR + 3 * QT) * 4;
    if (!attr_set) {
        cudaFuncSetAttribute(k_attn, cudaFuncAttributeMaxDynamicSharedMemorySize, ATTN_SMEM);
        attr_set = true;
    }

    k_detect<<<1, 256>>>(em);
    k_mask<<<(T_ * M_) / 256, 256>>>(em);
    k_compact<<<T_, 1024>>>();
    k_edges<<<dim3(T_, NJC, M_ / 256), 256>>>(A);
    k_nrm<<<(T_ * M_) / 256, 256>>>();
    k_tbias<<<T_, DH>>>(tw, tb, qw, qb, kw, kb, vw, vb);
    k_comb<<<16, 256>>>(ow, ob, fcw, fcb);
    k_gemm_z<<<dim3(T_, M_ / 64), 256>>>(x, w1, 0);
    k_spmm<<<dim3(T_, M_), DH>>>(b1);
    k_gemm_z<<<dim3(T_, M_ / 64), 256>>>(nullptr, w2, 1);
    k_spmm<<<dim3(T_, M_), DH>>>(b2);
    k_gemm_qkv<<<dim3(T_, M_ / 64, 3), 256>>>(qw, kw, vw);
    k_attn<<<dim3(T_, M_ / QT), 256, ATTN_SMEM>>>();
    cudaMemsetAsync(d_out, 0, (size_t)out_size * sizeof(float));
    k_out2<<<dim3(T_, M_ / 64), 256>>>((float*)d_out);
}